// round 2
// baseline (speedup 1.0000x reference)
#include <cuda_runtime.h>
#include <cuda_bf16.h>
#include <math.h>

// Problem constants
#define Bsz   16
#define CH    32          // WIDTH
#define DCH   3
#define S     128
#define HH    255         // 2s-1
#define WW    255
#define NPIX  (HH*WW)     // 65025
#define M12   12
#define KX24  24
#define TOT   (Bsz*CH*NPIX)   // 33,292,800
#define BN_EPS 1e-5f

// ---------------- scratch (static device globals; no allocation) ----------------
__device__ float  g_h[TOT];                 // fc0 output (layer-0 input), 133 MB
__device__ float  g_t[TOT];                 // pre-BN accum of last layer, 133 MB
__device__ float2 g_Y [Bsz*CH*HH*M12];      // fwd DFT along w
__device__ float2 g_Z [Bsz*CH*KX24*M12];    // fwd DFT along h (288 pts)
__device__ float2 g_Zm[Bsz*CH*KX24*M12];    // after mode mix
__device__ float2 g_Yi[Bsz*CH*HH*M12];      // inverse along h
__device__ float2 g_tw[WW];                 // e^{+i 2pi t/255}
__device__ float  g_sum[CH], g_sumsq[CH];
__device__ float  g_scale[CH], g_shift[CH];

// ---------------- init: twiddles + zero stats ----------------
__global__ void k_init() {
    int t = threadIdx.x;
    for (int i = t; i < WW; i += blockDim.x) {
        float a = 2.0f * (float)i / 255.0f;
        g_tw[i] = make_float2(cospif(a), sinpif(a));
    }
    if (t < CH) { g_sum[t] = 0.f; g_sumsq[t] = 0.f; }
}

// ---------------- K0: mirror + fc0 lift (3 -> 32) ----------------
__global__ void k0_fc0(const float* __restrict__ x,
                       const float* __restrict__ fc0_w,   // (3,32)
                       const float* __restrict__ fc0_b) { // (32,)
    __shared__ float sW[DCH*CH];
    __shared__ float sB[CH];
    if (threadIdx.x < DCH*CH) sW[threadIdx.x] = fc0_w[threadIdx.x];
    if (threadIdx.x < CH)     sB[threadIdx.x] = fc0_b[threadIdx.x];
    __syncthreads();

    int g = blockIdx.x * blockDim.x + threadIdx.x;
    if (g >= Bsz * NPIX) return;
    int b = g / NPIX, p = g % NPIX;
    int i = p / WW, j = p % WW;
    int sr = (i < S-1) ? (S-1 - i) : (i - (S-1));
    int sc = (j < S-1) ? (S-1 - j) : (j - (S-1));
    float sign = ((i < S-1) == (j < S-1)) ? 1.0f : -1.0f;

    float v[DCH];
#pragma unroll
    for (int c = 0; c < DCH; c++)
        v[c] = sign * x[((b*DCH + c)*S + sr)*S + sc];

#pragma unroll
    for (int d = 0; d < CH; d++) {
        float acc = sB[d];
#pragma unroll
        for (int c = 0; c < DCH; c++) acc += v[c] * sW[c*CH + d];
        g_h[(b*CH + d)*NPIX + p] = acc;
    }
}

// ---------------- K1: forward DFT along w (255 -> 12), one warp per row ----------------
// prev_bn=0: read g_h directly (layer 0).
// prev_bn=1: read relu(g_t * scale + shift)  — BN+ReLU of previous layer folded in.
__global__ void k1_fwd_w(int prev_bn) {
    __shared__ float2 tw[WW];
    for (int t = threadIdx.x; t < WW; t += blockDim.x) tw[t] = g_tw[t];
    __syncthreads();

    int warp = threadIdx.x >> 5, lane = threadIdx.x & 31;
    int r = blockIdx.x * 8 + warp;              // row over B*C*255
    if (r >= Bsz*CH*HH) return;
    const float* row = (prev_bn ? g_t : g_h) + (size_t)r * WW;
    float scl = 1.f, shf = 0.f;
    if (prev_bn) { int c = (r / HH) & (CH-1); scl = g_scale[c]; shf = g_shift[c]; }

    float ar[M12], ai[M12];
#pragma unroll
    for (int k = 0; k < M12; k++) { ar[k] = 0.f; ai[k] = 0.f; }

    for (int w = lane; w < WW; w += 32) {
        float v = row[w];
        if (prev_bn) v = fmaxf(v * scl + shf, 0.f);
        int idx = 0;
#pragma unroll
        for (int k = 0; k < M12; k++) {
            float2 e = tw[idx];
            ar[k] += v * e.x;          // conj twiddle e^{-i}
            ai[k] -= v * e.y;
            idx += w; if (idx >= WW) idx -= WW;
        }
    }
#pragma unroll
    for (int k = 0; k < M12; k++) {
#pragma unroll
        for (int off = 16; off > 0; off >>= 1) {
            ar[k] += __shfl_down_sync(0xffffffffu, ar[k], off);
            ai[k] += __shfl_down_sync(0xffffffffu, ai[k], off);
        }
    }
    if (lane == 0) {
#pragma unroll
        for (int k = 0; k < M12; k++)
            g_Y[(size_t)r*M12 + k] = make_float2(ar[k], ai[k]);
    }
}

// ---------------- K2: forward DFT along h (255 -> 24), one block per (b,c) ----------------
__global__ void k2_fwd_h() {
    __shared__ float2 sY[HH*M12];   // 24 KB
    __shared__ float2 tw[WW];
    int bc = blockIdx.x;
    const float2* Y = g_Y + (size_t)bc * HH * M12;
    for (int t = threadIdx.x; t < WW; t += blockDim.x) tw[t] = g_tw[t];
    for (int t = threadIdx.x; t < HH*M12; t += blockDim.x) sY[t] = Y[t];
    __syncthreads();

    int t = threadIdx.x;
    if (t < KX24*M12) {
        int kxi = t / M12, ky = t % M12;
        int kx = (kxi < M12) ? kxi : (231 + kxi);   // 243 + (kxi-12)
        float zr = 0.f, zi = 0.f;
        int idx = 0;
        for (int hh = 0; hh < HH; hh++) {
            float2 y = sY[hh*M12 + ky];
            float2 e = tw[idx];
            zr += y.x*e.x + y.y*e.y;    // y * conj(e)
            zi += y.y*e.x - y.x*e.y;
            idx += kx; if (idx >= WW) idx -= WW;
        }
        g_Z[(size_t)bc*(KX24*M12) + t] = make_float2(zr, zi);
    }
}

// ---------------- K3: mode mix, one block per freq point, 16 batch x 32 out ----------------
__global__ void k3_mix(const float* __restrict__ spec_w, int layer) {
    __shared__ float2 sZ[Bsz*CH];
    int f = blockIdx.x;                 // 0..287
    int kxi = f / M12, ky = f % M12;
    int region = (kxi < M12) ? 0 : 1;
    int xx = (kxi < M12) ? kxi : (kxi - M12);

    int tb = threadIdx.x / CH;          // batch 0..15
    int o  = threadIdx.x % CH;          // out channel
    sZ[tb*CH + o] = g_Z[((size_t)(tb*CH + o))*(KX24*M12) + f];
    __syncthreads();

    const float* Wb = spec_w + (size_t)(layer*2 + region)*CH*CH*M12*M12*2
                             + (size_t)(xx*M12 + ky)*2;
    float orr = 0.f, oii = 0.f;
#pragma unroll 4
    for (int i = 0; i < CH; i++) {
        float2 z = sZ[tb*CH + i];
        const float* wp = Wb + (size_t)(i*CH + o)*(M12*M12*2);
        float wr = wp[0], wi = wp[1];
        orr += z.x*wr - z.y*wi;
        oii += z.x*wi + z.y*wr;
    }
    g_Zm[((size_t)(tb*CH + o))*(KX24*M12) + f] = make_float2(orr, oii);
}

// ---------------- K4: inverse DFT along h (24 -> 255), one block per (b,c) ----------------
__global__ void k4_inv_h() {
    __shared__ float2 sZ[KX24*M12];
    __shared__ float2 tw[WW];
    int bc = blockIdx.x;
    for (int t = threadIdx.x; t < KX24*M12; t += blockDim.x)
        sZ[t] = g_Zm[(size_t)bc*(KX24*M12) + t];
    for (int t = threadIdx.x; t < WW; t += blockDim.x) tw[t] = g_tw[t];
    __syncthreads();

    for (int t = threadIdx.x; t < HH*M12; t += blockDim.x) {
        int hh = t / M12, ky = t % M12;
        float yr = 0.f, yi = 0.f;
#pragma unroll
        for (int kxi = 0; kxi < KX24; kxi++) {
            int kx = (kxi < M12) ? kxi : (231 + kxi);
            int idx = (kx * hh) % WW;
            float2 z = sZ[kxi*M12 + ky];
            float2 e = tw[idx];
            yr += z.x*e.x - z.y*e.y;    // z * e^{+i}
            yi += z.x*e.y + z.y*e.x;
        }
        g_Yi[(size_t)bc*HH*M12 + t] = make_float2(yr, yi);
    }
}

// ---------------- K5: fused inverse-w + 1x1 conv + bias + BN stats ----------------
// One block per (b, h-row). 256 threads: o = tid>>3 (out channel), wsub = tid&7.
// prev_bn folds the previous layer's BN+ReLU into the activation read.
__global__ void k5_invw_conv(const float* __restrict__ conv_w,  // (4,32,32)
                             const float* __restrict__ conv_b,  // (4,32)
                             int layer, int prev_bn) {
    __shared__ float  sH[CH][256];        // input row per channel (32 KB)
    __shared__ float  sYr[CH][13];        // pre-doubled, pre-scaled Yi (real)
    __shared__ float  sYi[CH][13];        // (imag)
    __shared__ float  sCw[CH][33];        // conv weights padded
    __shared__ float2 tw[WW];
    __shared__ float  sCb[CH];
    __shared__ float  sScl[CH], sShf[CH];
    __shared__ float  ssum[CH], ssq[CH];

    int bh = blockIdx.x;
    int b = bh / HH, hh = bh % HH;

    for (int t = threadIdx.x; t < WW; t += 256) tw[t] = g_tw[t];
    for (int t = threadIdx.x; t < CH*CH; t += 256)
        sCw[t/CH][t%CH] = conv_w[layer*CH*CH + t];
    if (threadIdx.x < CH) {
        sCb[threadIdx.x] = conv_b[layer*CH + threadIdx.x];
        sScl[threadIdx.x] = prev_bn ? g_scale[threadIdx.x] : 1.f;
        sShf[threadIdx.x] = prev_bn ? g_shift[threadIdx.x] : 0.f;
        ssum[threadIdx.x] = 0.f; ssq[threadIdx.x] = 0.f;
    }
    __syncthreads();
    const float* src = prev_bn ? g_t : g_h;
    for (int t = threadIdx.x; t < CH*WW; t += 256) {
        int c = t / WW, w = t % WW;
        float v = src[((size_t)(b*CH + c)*HH + hh)*WW + w];
        if (prev_bn) v = fmaxf(v * sScl[c] + sShf[c], 0.f);
        sH[c][w] = v;
    }
    const float dsc = 1.0f / 65025.0f;
    for (int t = threadIdx.x; t < CH*M12; t += 256) {
        int c = t / M12, ky = t % M12;
        float2 y = g_Yi[((size_t)(b*CH + c)*HH + hh)*M12 + ky];
        float f = (ky == 0) ? dsc : 2.0f*dsc;     // irfft doubling + ortho scale
        sYr[c][ky] = y.x * f;
        sYi[c][ky] = y.y * f;
    }
    __syncthreads();

    int o    = threadIdx.x >> 3;
    int wsub = threadIdx.x & 7;
    float lsum = 0.f, lsq = 0.f;
    float cb = sCb[o];

    for (int it = 0; it < 32; it++) {
        int w = wsub + it*8;
        if (w < WW) {
            // spectral: Re( sum_ky Yi * e^{+i 2pi ky w/255} )  (scale folded in)
            float acc = cb;
            int ti = 0;
#pragma unroll
            for (int ky = 0; ky < M12; ky++) {
                float2 e = tw[ti];
                acc += sYr[o][ky]*e.x - sYi[o][ky]*e.y;
                ti += w; if (ti >= WW) ti -= WW;
            }
            // 1x1 conv
#pragma unroll
            for (int c = 0; c < CH; c++) acc += sH[c][w] * sCw[o][c];
            g_t[((size_t)(b*CH + o)*HH + hh)*WW + w] = acc;
            lsum += acc; lsq += acc*acc;
        }
    }
    atomicAdd(&ssum[o], lsum);
    atomicAdd(&ssq[o],  lsq);
    __syncthreads();
    if (threadIdx.x < CH) {
        atomicAdd(&g_sum[threadIdx.x],   ssum[threadIdx.x]);
        atomicAdd(&g_sumsq[threadIdx.x], ssq[threadIdx.x]);
    }
}

// ---------------- K6: finalize BN stats -> scale/shift; reset accumulators ----------------
__global__ void k6_bn(const float* __restrict__ bn_g, const float* __restrict__ bn_b,
                      int layer) {
    int c = threadIdx.x;
    if (c < CH) {
        const float N = (float)Bsz * (float)NPIX;
        float mean = g_sum[c] / N;
        float var  = g_sumsq[c] / N - mean*mean;
        float inv  = rsqrtf(var + BN_EPS);
        float gg = bn_g[layer*CH + c], bb = bn_b[layer*CH + c];
        g_scale[c] = gg * inv;
        g_shift[c] = bb - gg * inv * mean;
        g_sum[c] = 0.f; g_sumsq[c] = 0.f;
    }
}

// ---------------- K8: head — BN affine (layer 3, no relu) + fc1/relu + fc2, quadrant only ----------------
__global__ void k8_head(const float* __restrict__ fc1_w,  // (32,128)
                        const float* __restrict__ fc1_b,  // (128,)
                        const float* __restrict__ fc2_w,  // (128,1)
                        const float* __restrict__ fc2_b,  // (1,)
                        float* __restrict__ out) {
    __shared__ float W1[CH][128];    // 16 KB
    __shared__ float b1[128];
    __shared__ float W2[128];
    __shared__ float sc[CH], sh[CH];

    for (int t = threadIdx.x; t < CH*128; t += blockDim.x)
        W1[t/128][t%128] = fc1_w[t];
    if (threadIdx.x < 128) { b1[threadIdx.x] = fc1_b[threadIdx.x]; W2[threadIdx.x] = fc2_w[threadIdx.x]; }
    if (threadIdx.x < CH)  { sc[threadIdx.x] = g_scale[threadIdx.x]; sh[threadIdx.x] = g_shift[threadIdx.x]; }
    __syncthreads();

    int p = blockIdx.x * blockDim.x + threadIdx.x;     // over 16*128*128
    if (p >= Bsz*S*S) return;
    int b = p >> 14, q = p & 16383;
    int ii = q >> 7, jj = q & 127;
    int i = ii + (S-1), j = jj + (S-1);

    float in[CH];
#pragma unroll
    for (int c = 0; c < CH; c++)
        in[c] = g_t[((size_t)(b*CH + c)*HH + i)*WW + j] * sc[c] + sh[c];

    float acc = fc2_b[0];
#pragma unroll 4
    for (int d = 0; d < 128; d++) {
        float a = b1[d];
#pragma unroll
        for (int c = 0; c < CH; c++) a += in[c] * W1[c][d];
        a = fmaxf(a, 0.f);
        acc += a * W2[d];
    }
#pragma unroll
    for (int c3 = 0; c3 < DCH; c3++)
        out[((b*DCH + c3)*S + ii)*S + jj] = acc;
}

// ---------------- launch ----------------
extern "C" void kernel_launch(void* const* d_in, const int* in_sizes, int n_in,
                              void* d_out, int out_size) {
    const float* x      = (const float*)d_in[0];
    const float* fc0_w  = (const float*)d_in[1];
    const float* fc0_b  = (const float*)d_in[2];
    const float* spec_w = (const float*)d_in[3];
    const float* conv_w = (const float*)d_in[4];
    const float* conv_b = (const float*)d_in[5];
    const float* bn_g   = (const float*)d_in[6];
    const float* bn_b   = (const float*)d_in[7];
    const float* fc1_w  = (const float*)d_in[8];
    const float* fc1_b  = (const float*)d_in[9];
    const float* fc2_w  = (const float*)d_in[10];
    const float* fc2_b  = (const float*)d_in[11];
    float* out = (float*)d_out;

    k_init<<<1, 256>>>();
    k0_fc0<<<(Bsz*NPIX + 255)/256, 256>>>(x, fc0_w, fc0_b);

    for (int layer = 0; layer < 4; layer++) {
        int prev_bn = (layer > 0) ? 1 : 0;
        k1_fwd_w<<<(Bsz*CH*HH + 7)/8, 256>>>(prev_bn);
        k2_fwd_h<<<Bsz*CH, 288>>>();
        k3_mix<<<KX24*M12, Bsz*CH>>>(spec_w, layer);
        k4_inv_h<<<Bsz*CH, 256>>>();
        k5_invw_conv<<<Bsz*HH, 256>>>(conv_w, conv_b, layer, prev_bn);
        k6_bn<<<1, 32>>>(bn_g, bn_b, layer);
    }
    k8_head<<<(Bsz*S*S + 127)/128, 128>>>(fc1_w, fc1_b, fc2_w, fc2_b, out);
}

// round 3
// speedup vs baseline: 1.2506x; 1.2506x over previous
#include <cuda_runtime.h>
#include <cuda_bf16.h>
#include <math.h>

// Problem constants
#define Bsz   16
#define CH    32
#define DCH   3
#define S     128
#define HH    255
#define WW    255
#define WP    256                  // padded row stride (16B-aligned float4 rows)
#define NPIX  (HH*WW)              // 65025
#define M12   12
#define KX24  24
#define ROWS  (Bsz*CH*HH)          // 130560
#define TOTP  ((size_t)ROWS*WP)    // padded activation size
#define BN_EPS 1e-5f

// ---------------- scratch ----------------
__device__ float  g_h[Bsz*CH*HH*WP];        // fc0 output (padded rows), ~134 MB
__device__ float  g_t[Bsz*CH*HH*WP];        // pre-BN accum (padded rows), ~134 MB
__device__ float2 g_Y [ROWS*M12];           // fwd DFT along w
__device__ float2 g_Z [Bsz*CH*KX24*M12];    // fwd DFT along h
__device__ float2 g_Zm[Bsz*CH*KX24*M12];    // after mode mix
__device__ float2 g_Yi[ROWS*M12];           // inverse along h
__device__ float2 g_ET[13*256];             // e^{-i 2pi k t/255}, k=0..12, t=0..254 (t=255 -> 0)
__device__ float  g_sum[CH], g_sumsq[CH];
__device__ float  g_scale[CH], g_shift[CH];

// ---------------- init: twiddle table + zero stats ----------------
__global__ void k_init() {
    int t = blockIdx.x * blockDim.x + threadIdx.x;
    if (t < 13*256) {
        int k = t >> 8, w = t & 255;
        float2 e = make_float2(0.f, 0.f);
        if (w < 255) {
            int m = (k * w) % 255;
            float a = 2.0f * (float)m / 255.0f;
            e = make_float2(cospif(a), -sinpif(a));   // e^{-i theta}
        }
        g_ET[t] = e;
    }
    if (t < CH) { g_sum[t] = 0.f; g_sumsq[t] = 0.f; }
}

// ---------------- K0: mirror + fc0 lift (3 -> 32) ----------------
__global__ void k0_fc0(const float* __restrict__ x,
                       const float* __restrict__ fc0_w,
                       const float* __restrict__ fc0_b) {
    __shared__ float sW[DCH*CH];
    __shared__ float sB[CH];
    if (threadIdx.x < DCH*CH) sW[threadIdx.x] = fc0_w[threadIdx.x];
    if (threadIdx.x < CH)     sB[threadIdx.x] = fc0_b[threadIdx.x];
    __syncthreads();

    int g = blockIdx.x * blockDim.x + threadIdx.x;
    if (g >= Bsz * NPIX) return;
    int b = g / NPIX, p = g % NPIX;
    int i = p / WW, j = p % WW;
    int sr = (i < S-1) ? (S-1 - i) : (i - (S-1));
    int sc = (j < S-1) ? (S-1 - j) : (j - (S-1));
    float sign = ((i < S-1) == (j < S-1)) ? 1.0f : -1.0f;

    float v[DCH];
#pragma unroll
    for (int c = 0; c < DCH; c++)
        v[c] = sign * x[((b*DCH + c)*S + sr)*S + sc];

#pragma unroll
    for (int d = 0; d < CH; d++) {
        float acc = sB[d];
#pragma unroll
        for (int c = 0; c < DCH; c++) acc += v[c] * sW[c*CH + d];
        g_h[((size_t)(b*CH + d)*HH + i)*WP + j] = acc;
    }
}

// ---------------- K1: forward DFT along w (255 -> 12), 4 rows per warp ----------------
__global__ __launch_bounds__(256) void k1_fwd_w(int prev_bn) {
    __shared__ float2 sE[12*256];       // 24 KB
    for (int t = threadIdx.x; t < 12*256; t += 256) sE[t] = g_ET[t];
    __syncthreads();

    int wid = threadIdx.x >> 5, lane = threadIdx.x & 31;
    int rb = (blockIdx.x * 8 + wid) * 4;
    const float* src = prev_bn ? g_t : g_h;

    const float* rp[4];
    float scl[4], shf[4];
#pragma unroll
    for (int j = 0; j < 4; j++) {
        int r = rb + j;
        rp[j] = src + (size_t)r * WP;
        if (prev_bn) { int c = (r / HH) & (CH-1); scl[j] = g_scale[c]; shf[j] = g_shift[c]; }
        else { scl[j] = 1.f; shf[j] = 0.f; }
    }

    float2 acc[4][M12];
#pragma unroll
    for (int j = 0; j < 4; j++)
#pragma unroll
        for (int k = 0; k < M12; k++) acc[j][k] = make_float2(0.f, 0.f);

#pragma unroll
    for (int it = 0; it < 8; it++) {
        int w = lane + it*32;
        float v[4];
#pragma unroll
        for (int j = 0; j < 4; j++) {
            float xv = (w < WW) ? rp[j][w] : 0.f;
            if (prev_bn) xv = fmaxf(xv * scl[j] + shf[j], 0.f);
            v[j] = xv;
        }
#pragma unroll
        for (int k = 0; k < M12; k++) {
            float2 e = sE[k*256 + w];
#pragma unroll
            for (int j = 0; j < 4; j++) {
                acc[j][k].x += v[j] * e.x;
                acc[j][k].y += v[j] * e.y;
            }
        }
    }

#pragma unroll
    for (int j = 0; j < 4; j++)
#pragma unroll
        for (int k = 0; k < M12; k++) {
            float xr = acc[j][k].x, xi = acc[j][k].y;
#pragma unroll
            for (int o = 16; o > 0; o >>= 1) {
                xr += __shfl_xor_sync(0xffffffffu, xr, o);
                xi += __shfl_xor_sync(0xffffffffu, xi, o);
            }
            if (lane == 0) g_Y[(size_t)(rb + j)*M12 + k] = make_float2(xr, xi);
        }
}

// ---------------- K2: forward DFT along h (255 -> 24), table-driven, two E phases ----------------
__global__ __launch_bounds__(288) void k2_fwd_h() {
    __shared__ float2 sY[HH*M12];       // 24480 B
    __shared__ float2 sE[13*128];       // 13312 B
    int bc = blockIdx.x;
    for (int t = threadIdx.x; t < HH*M12; t += 288)
        sY[t] = g_Y[(size_t)bc*HH*M12 + t];

    int t = threadIdx.x;                // 0..287
    int kxi = t / M12, ky = t % M12;
    int kr  = (kxi < M12) ? kxi : (24 - kxi);
    float sg = (kxi < M12) ? 1.f : -1.f;

    float zr = 0.f, zi = 0.f;
    for (int ph = 0; ph < 2; ph++) {
        __syncthreads();
        for (int u = threadIdx.x; u < 13*128; u += 288) {
            int k = u / 128, hl = u % 128;
            sE[u] = g_ET[k*256 + ph*128 + hl];
        }
        __syncthreads();
        int h0 = ph*128, h1 = ph ? HH : 128;
#pragma unroll 4
        for (int h = h0; h < h1; h++) {
            float2 y = sY[h*M12 + ky];
            float2 e = sE[kr*128 + (h - h0)];
            float ey = e.y * sg;        // actual E = (e.x, ey) = e^{-i theta}
            zr += y.x*e.x - y.y*ey;
            zi += y.x*ey + y.y*e.x;
        }
    }
    g_Z[(size_t)bc*(KX24*M12) + t] = make_float2(zr, zi);
}

// ---------------- K3: mode mix ----------------
__global__ void k3_mix(const float* __restrict__ spec_w, int layer) {
    __shared__ float2 sZ[Bsz*CH];
    int f = blockIdx.x;
    int kxi = f / M12, ky = f % M12;
    int region = (kxi < M12) ? 0 : 1;
    int xx = (kxi < M12) ? kxi : (kxi - M12);

    int tb = threadIdx.x / CH;
    int o  = threadIdx.x % CH;
    sZ[tb*CH + o] = g_Z[((size_t)(tb*CH + o))*(KX24*M12) + f];
    __syncthreads();

    const float* Wb = spec_w + (size_t)(layer*2 + region)*CH*CH*M12*M12*2
                             + (size_t)(xx*M12 + ky)*2;
    float orr = 0.f, oii = 0.f;
#pragma unroll 4
    for (int i = 0; i < CH; i++) {
        float2 z = sZ[tb*CH + i];
        const float* wp = Wb + (size_t)(i*CH + o)*(M12*M12*2);
        float wr = wp[0], wi = wp[1];
        orr += z.x*wr - z.y*wi;
        oii += z.x*wi + z.y*wr;
    }
    g_Zm[((size_t)(tb*CH + o))*(KX24*M12) + f] = make_float2(orr, oii);
}

// ---------------- K4: inverse DFT along h (24 -> 255), table-driven ----------------
__global__ __launch_bounds__(256) void k4_inv_h() {
    __shared__ float2 sZ[KX24*M12];     // 2304 B
    __shared__ float2 sE[13*256];       // 26624 B
    int bc = blockIdx.x;
    for (int t = threadIdx.x; t < KX24*M12; t += 256)
        sZ[t] = g_Zm[(size_t)bc*(KX24*M12) + t];
    for (int t = threadIdx.x; t < 13*256; t += 256) sE[t] = g_ET[t];
    __syncthreads();

    for (int t = threadIdx.x; t < HH*M12; t += 256) {
        int hh = t / M12, ky = t % M12;
        float yr = 0.f, yi = 0.f;
#pragma unroll
        for (int kxi = 0; kxi < KX24; kxi++) {
            int kr  = (kxi < M12) ? kxi : (24 - kxi);
            float sg = (kxi < M12) ? 1.f : -1.f;
            float2 z = sZ[kxi*M12 + ky];
            float2 e = sE[kr*256 + hh];
            float ey = e.y * sg;        // actual E = (e.x, ey)
            // Yi += z * conj(E) = z * (e.x, -ey)
            yr += z.x*e.x + z.y*ey;
            yi += z.y*e.x - z.x*ey;
        }
        g_Yi[((size_t)bc*HH + hh)*M12 + t % M12] = make_float2(yr, yi);
    }
}

// ---------------- K5: fused inverse-w + 1x1 conv + bias + BN stats ----------------
// Dynamic smem. 256 threads: o = tid>>3, wsub = tid&7; float4 over w.
__global__ __launch_bounds__(256) void k5_invw_conv(const float* __restrict__ conv_w,
                                                   const float* __restrict__ conv_b,
                                                   int layer, int prev_bn) {
    extern __shared__ float sm[];
    float*  sH   = sm;                         // 32*256 = 8192 floats
    float2* sE   = (float2*)(sm + 8192);       // 12*256 float2 = 6144 floats
    float*  sYr  = sm + 8192 + 6144;           // 384
    float*  sYi  = sYr + 384;                  // 384
    float*  sCw  = sYi + 384;                  // 1024
    float*  sCb  = sCw + 1024;                 // 32
    float*  ssum = sCb + 32;                   // 32
    float*  ssq  = ssum + 32;                  // 32
    float*  sScl = ssq + 32;                   // 32
    float*  sShf = sScl + 32;                  // 32

    int b = blockIdx.x / HH, hh = blockIdx.x % HH;
    int tid = threadIdx.x;

    for (int t = tid; t < 12*256; t += 256) sE[t] = g_ET[t];
    for (int t = tid; t < CH*CH; t += 256) sCw[t] = conv_w[layer*CH*CH + t];
    if (tid < CH) {
        sCb[tid]  = conv_b[layer*CH + tid];
        ssum[tid] = 0.f; ssq[tid] = 0.f;
        sScl[tid] = prev_bn ? g_scale[tid] : 1.f;
        sShf[tid] = prev_bn ? g_shift[tid] : 0.f;
    }
    __syncthreads();

    const float* src = prev_bn ? g_t : g_h;
    for (int t = tid; t < CH*256; t += 256) {
        int c = t >> 8, w = t & 255;
        float v = 0.f;
        if (w < WW) {
            v = src[((size_t)(b*CH + c)*HH + hh)*WP + w];
            if (prev_bn) v = fmaxf(v * sScl[c] + sShf[c], 0.f);
        }
        sH[t] = v;
    }
    const float dsc = 1.0f / 65025.0f;
    for (int t = tid; t < CH*M12; t += 256) {
        int c = t / M12, ky = t % M12;
        float2 y = g_Yi[((size_t)(b*CH + c)*HH + hh)*M12 + ky];
        float f = (ky == 0) ? dsc : 2.0f*dsc;
        sYr[t] = y.x * f;
        sYi[t] = y.y * f;
    }
    __syncthreads();

    int o = tid >> 3, wsub = tid & 7;
    float wr[CH];
#pragma unroll
    for (int c = 0; c < CH; c++) wr[c] = sCw[o*CH + c];
    float yrr[M12], yii[M12];
#pragma unroll
    for (int k = 0; k < M12; k++) { yrr[k] = sYr[o*M12 + k]; yii[k] = sYi[o*M12 + k]; }
    float cb = sCb[o];
    float lsum = 0.f, lsq = 0.f;
    float* orow = g_t + ((size_t)(b*CH + o)*HH + hh)*WP;

#pragma unroll
    for (int it = 0; it < 8; it++) {
        int wb = it*32 + wsub*4;
        float4 acc = make_float4(cb, cb, cb, cb);
        // spectral: Re(Y * e^{+i th}) = yr*E.x + yi*E.y with E = e^{-i th}
#pragma unroll
        for (int k = 0; k < M12; k++) {
            float4 eA = *(const float4*)&sE[k*256 + wb];
            float4 eB = *(const float4*)&sE[k*256 + wb + 2];
            acc.x += yrr[k]*eA.x + yii[k]*eA.y;
            acc.y += yrr[k]*eA.z + yii[k]*eA.w;
            acc.z += yrr[k]*eB.x + yii[k]*eB.y;
            acc.w += yrr[k]*eB.z + yii[k]*eB.w;
        }
        // 1x1 conv
#pragma unroll
        for (int c = 0; c < CH; c++) {
            float4 h4 = *(const float4*)&sH[c*256 + wb];
            float wc = wr[c];
            acc.x += h4.x*wc; acc.y += h4.y*wc; acc.z += h4.z*wc; acc.w += h4.w*wc;
        }
        if (wb == 252) acc.w = 0.f;     // w=255 pad column
        *(float4*)&orow[wb] = acc;
        lsum += acc.x + acc.y + acc.z + acc.w;
        lsq  += acc.x*acc.x + acc.y*acc.y + acc.z*acc.z + acc.w*acc.w;
    }
    atomicAdd(&ssum[o], lsum);
    atomicAdd(&ssq[o],  lsq);
    __syncthreads();
    if (tid < CH) {
        atomicAdd(&g_sum[tid],   ssum[tid]);
        atomicAdd(&g_sumsq[tid], ssq[tid]);
    }
}

// ---------------- K6: finalize BN stats ----------------
__global__ void k6_bn(const float* __restrict__ bn_g, const float* __restrict__ bn_b,
                      int layer) {
    int c = threadIdx.x;
    if (c < CH) {
        const float N = (float)Bsz * (float)NPIX;
        float mean = g_sum[c] / N;
        float var  = g_sumsq[c] / N - mean*mean;
        float inv  = rsqrtf(var + BN_EPS);
        float gg = bn_g[layer*CH + c], bb = bn_b[layer*CH + c];
        g_scale[c] = gg * inv;
        g_shift[c] = bb - gg * inv * mean;
        g_sum[c] = 0.f; g_sumsq[c] = 0.f;
    }
}

// ---------------- K8: head (BN affine + fc1/relu + fc2, quadrant only) ----------------
__global__ __launch_bounds__(128) void k8_head(const float* __restrict__ fc1_w,
                                               const float* __restrict__ fc1_b,
                                               const float* __restrict__ fc2_w,
                                               const float* __restrict__ fc2_b,
                                               float* __restrict__ out) {
    __shared__ float W1T[128][36];     // transposed fc1, padded row (16B-aligned)
    __shared__ float b1[128];
    __shared__ float W2[128];
    __shared__ float sc[CH], sh[CH];

    for (int t = threadIdx.x; t < CH*128; t += 128) {
        int c = t >> 7, d = t & 127;
        W1T[d][c] = fc1_w[t];
    }
    b1[threadIdx.x] = fc1_b[threadIdx.x];
    W2[threadIdx.x] = fc2_w[threadIdx.x];
    if (threadIdx.x < CH) { sc[threadIdx.x] = g_scale[threadIdx.x]; sh[threadIdx.x] = g_shift[threadIdx.x]; }
    __syncthreads();

    int p = blockIdx.x * 128 + threadIdx.x;
    if (p >= Bsz*S*S) return;
    int b = p >> 14, q = p & 16383;
    int ii = q >> 7, jj = q & 127;
    int i = ii + (S-1), j = jj + (S-1);

    float in[CH];
#pragma unroll
    for (int c = 0; c < CH; c++)
        in[c] = g_t[((size_t)(b*CH + c)*HH + i)*WP + j] * sc[c] + sh[c];

    float acc = fc2_b[0];
#pragma unroll 2
    for (int d = 0; d < 128; d++) {
        float a = b1[d];
#pragma unroll
        for (int c4 = 0; c4 < CH; c4 += 4) {
            float4 w4 = *(const float4*)&W1T[d][c4];
            a += in[c4]*w4.x + in[c4+1]*w4.y + in[c4+2]*w4.z + in[c4+3]*w4.w;
        }
        a = fmaxf(a, 0.f);
        acc += a * W2[d];
    }
#pragma unroll
    for (int c3 = 0; c3 < DCH; c3++)
        out[((b*DCH + c3)*S + ii)*S + jj] = acc;
}

// ---------------- launch ----------------
extern "C" void kernel_launch(void* const* d_in, const int* in_sizes, int n_in,
                              void* d_out, int out_size) {
    const float* x      = (const float*)d_in[0];
    const float* fc0_w  = (const float*)d_in[1];
    const float* fc0_b  = (const float*)d_in[2];
    const float* spec_w = (const float*)d_in[3];
    const float* conv_w = (const float*)d_in[4];
    const float* conv_b = (const float*)d_in[5];
    const float* bn_g   = (const float*)d_in[6];
    const float* bn_b   = (const float*)d_in[7];
    const float* fc1_w  = (const float*)d_in[8];
    const float* fc1_b  = (const float*)d_in[9];
    const float* fc2_w  = (const float*)d_in[10];
    const float* fc2_b  = (const float*)d_in[11];
    float* out = (float*)d_out;

    const int K5_SMEM = (8192 + 6144 + 384 + 384 + 1024 + 32*5) * 4;   // 65152 B
    cudaFuncSetAttribute(k5_invw_conv, cudaFuncAttributeMaxDynamicSharedMemorySize, K5_SMEM);

    k_init<<<13, 256>>>();
    k0_fc0<<<(Bsz*NPIX + 255)/256, 256>>>(x, fc0_w, fc0_b);

    for (int layer = 0; layer < 4; layer++) {
        int prev_bn = (layer > 0) ? 1 : 0;
        k1_fwd_w<<<ROWS/32, 256>>>(prev_bn);
        k2_fwd_h<<<Bsz*CH, 288>>>();
        k3_mix<<<KX24*M12, Bsz*CH>>>(spec_w, layer);
        k4_inv_h<<<Bsz*CH, 256>>>();
        k5_invw_conv<<<Bsz*HH, 256, K5_SMEM>>>(conv_w, conv_b, layer, prev_bn);
        k6_bn<<<1, 32>>>(bn_g, bn_b, layer);
    }
    k8_head<<<(Bsz*S*S + 127)/128, 128>>>(fc1_w, fc1_b, fc2_w, fc2_b, out);
}